// round 16
// baseline (speedup 1.0000x reference)
#include <cuda_runtime.h>
#include <cstdint>

#define T_LEN   730
#define B_LEN   1000
#define LENF    15
#define NEARZERO 1e-5f

#define NBLK  125                // 8 basins per block
#define BLK_T 128                // warps 0,1: producers; warp2: conv; warp3: sums
#define UG 10
#define NGROUPS 73               // 73*10 = 730

// smem layout: per (slot, step, basin): channel m's float4 (avail,Snew,Gnew,vae)
// at float offset m*4; basin stride 36 floats (pad 4) for bank-conflict freedom.
#define BAS_S  36
#define STEP_S (BAS_S * 8)       // 288 floats
#define SLOT_S (STEP_S * UG)     // 2880 floats
#define SRED_FLOATS (2 * SLOT_S) // 5760 floats = 23040 B

__device__ __forceinline__ float f_sqrt_approx(float x) {
    float r; asm("sqrt.approx.f32 %0, %1;" : "=f"(r) : "f"(x)); return r;
}
__device__ __forceinline__ float f_ex2(float x) {
    float r; asm("ex2.approx.f32 %0, %1;" : "=f"(r) : "f"(x)); return r;
}

// named barriers: 64 producers + 64 consumers (warps 2,3) = 128 arrivals
#define BAR_SYNC(id)   asm volatile("bar.sync %0, 128;"   :: "r"(id) : "memory")
#define BAR_ARRIVE(id) asm volatile("bar.arrive %0, 128;" :: "r"(id) : "memory")

__global__ void __launch_bounds__(BLK_T) fused_kernel(
    const float* __restrict__ x,      // (T,B,2)
    const float* __restrict__ raw,    // (B,34)
    float* __restrict__ out)          // (T,B,6)
{
    __shared__ __align__(16) float sred[SRED_FLOATS];
    const int tid = threadIdx.x;

    if (tid < 64) {
        // ====== producers: 1 chain/thread, Y-state short chain, 1 STS.128 ======
        int bl = tid >> 3;
        int m  = tid & 7;
        int b  = blockIdx.x * 8 + bl;

        float a   = fmaf(raw[b*34 +      m], 0.9f, 0.1f);
        float bb  = fmaf(raw[b*34 +  8 + m], 450.0f, 50.0f);
        float c   = raw[b*34 + 16 + m];
        float d   = fmaf(raw[b*34 + 24 + m], 0.89f, 0.01f);

        float inv2a  = 0.5f / a;
        float binv2a = bb * inv2a;
        float boa    = bb / a;
        float nl2eob = -1.44269504088896f / bb;   // -log2(e)/b
        float inv1pd = 1.0f / (1.0f + d);

        // carried state: Y_prev, ef_prev (S = Yp*efp); init S=50 -> Yp=50, efp=1
        float Yp  = 50.0f;
        float efp = 1.0f;
        float G   = 10.0f;

        float4* myv = (float4*)(sred + bl * BAS_S + m * 4);
        const float2* __restrict__ xv = (const float2*)x;

        float2 cur[UG], nxt[UG];

#define LOADG(buf, grp) do {                                          \
        const float2* _bp = xv + (grp) * UG * B_LEN + b;              \
        _Pragma("unroll")                                             \
        for (int _i = 0; _i < UG; ++_i) buf[_i] = __ldg(_bp + _i * B_LEN); \
    } while (0)

#define PBODY(buf, gi_) do {                                          \
        int slot = (gi_) & 1;                                         \
        if ((gi_) >= 2) BAR_SYNC(3 + slot);                           \
        float4* sv = myv + slot * (SLOT_S / 4);                       \
        _Pragma("unroll")                                             \
        for (int i = 0; i < UG; ++i) {                                \
            float p   = buf[i].x;                                     \
            float pet = buf[i].y;                                     \
            float c1 = fmaf(p, inv2a, binv2a);                        \
            float c2 = p * boa;                                       \
            float eA = efp * inv2a;                                   \
            float eB = efp * boa;                                     \
            float term = fmaf(Yp, eA, c1);                            \
            float wboa = fmaf(Yp, eB, c2);                            \
            float arg  = fmaxf(fmaf(term, term, -wboa), NEARZERO);    \
            float Y    = term - f_sqrt_approx(arg);                   \
            float ef   = f_ex2(pet * nl2eob);                         \
            float S    = Yp * efp;                                    \
            float W    = p + S;                                       \
            float avail = W - Y;                                      \
            float Snew = Y * ef;                                      \
            float Gnew = fmaf(c, avail, G) * inv1pd;                  \
            float vae  = Y - Snew;                                    \
            G = Gnew; Yp = Y; efp = ef;                               \
            sv[i * (STEP_S / 4)] = make_float4(avail, Snew, Gnew, vae); \
        }                                                             \
        BAR_ARRIVE(1 + slot);                                         \
    } while (0)

        LOADG(cur, 0);
        for (int gi = 0; gi < NGROUPS; gi += 2) {
            if (gi + 1 < NGROUPS) LOADG(nxt, gi + 1);
            PBODY(cur, gi);
            if (gi + 1 >= NGROUPS) break;
            if (gi + 2 < NGROUPS) LOADG(cur, gi + 2);
            PBODY(nxt, gi + 1);
        }
#undef PBODY
#undef LOADG
    } else if (tid < 96) {
        // ========= warp2: inline convolution lanes =========
        // lane 0..7 : qsurf series (dot avail with (1-c)), stores cols 0,1
        // lane 8..15: qgw   series (dot Gnew  with d),     stores col 2
        int lane   = tid - 64;
        bool active = (lane < 16);
        int bl     = lane & 7;
        int series = lane >> 3;
        int b      = blockIdx.x * 8 + bl;

        // per-channel dot weights
        float wgt[8];
#pragma unroll
        for (int k = 0; k < 8; ++k) {
            float ck = raw[b*34 + 16 + k];
            float dk = fmaf(raw[b*34 + 24 + k], 0.89f, 0.01f);
            wgt[k] = (series == 0) ? (1.0f - ck) : dk;
        }
        int comp = (series == 0) ? 0 : 2;     // avail or Gnew

        // gamma unit hydrograph, pre-scaled by 1/8
        float uh[LENF];
        if (active) {
            float ra = raw[b * 34 + 32] * 2.9f;
            float rb = raw[b * 34 + 33] * 6.5f;
            float aa    = fmaxf(ra, 0.0f) + 0.1f;
            float theta = fmaxf(rb, 0.0f) + 0.5f;
            float lg   = lgammaf(aa);
            float lth  = logf(theta);
            float ivth = 1.0f / theta;
            float s = 0.0f;
#pragma unroll
            for (int k = 0; k < LENF; ++k) {
                float t = (float)k + 0.5f;
                float lw = (aa - 1.0f) * logf(t) - t * ivth - lg - aa * lth;
                uh[k] = expf(lw);
                s += uh[k];
            }
            float inv = 0.125f / s;
#pragma unroll
            for (int k = 0; k < LENF; ++k) uh[k] *= inv;
        } else {
#pragma unroll
            for (int k = 0; k < LENF; ++k) uh[k] = 0.0f;
        }

        float r[LENF - 1];
#pragma unroll
        for (int k = 0; k < LENF - 1; ++k) r[k] = 0.0f;

        const float* base0 = sred + bl * BAS_S + comp;

        for (int gi = 0; gi < NGROUPS; ++gi) {
            int slot = gi & 1;
            BAR_SYNC(1 + slot);
            if (active) {
                const float* sb = base0 + slot * SLOT_S;
                int tbase = gi * UG;
#pragma unroll
                for (int i = 0; i < UG; ++i) {
                    const float* sl = sb + i * STEP_S;
                    float q = wgt[0] * sl[0];
#pragma unroll
                    for (int k = 1; k < 8; ++k)
                        q = fmaf(wgt[k], sl[k * 4], q);

                    float mine = fmaf(q, uh[0], r[0]);
#pragma unroll
                    for (int j = 0; j < LENF - 2; ++j)
                        r[j] = fmaf(q, uh[j + 1], r[j + 1]);
                    r[LENF - 2] = q * uh[LENF - 1];

                    float other = __shfl_xor_sync(0xffffu, mine, 8);
                    int t = tbase + i;
                    float* o = out + t * (6 * B_LEN) + b * 6;
                    if (series == 0) {
                        *(float2*)o = make_float2(mine + other, mine);
                    } else {
                        o[2] = mine;
                    }
                }
            }
            BAR_ARRIVE(3 + slot);
        }
    } else {
        // ========= warp3: plain mean lanes (cols 3,4,5) =========
        int lane = tid - 96;
        bool active = (lane < 24);
        int bl = lane & 7;
        int j  = lane >> 3;                  // 0: AET(comp3), 1: S(comp1), 2: G(comp2)
        int b  = blockIdx.x * 8 + bl;
        int comp = (j == 0) ? 3 : ((j == 1) ? 1 : 2);

        const float* base0 = sred + bl * BAS_S + comp;

        for (int gi = 0; gi < NGROUPS; ++gi) {
            int slot = gi & 1;
            BAR_SYNC(1 + slot);
            if (active) {
                const float* sb = base0 + slot * SLOT_S;
                int tbase = gi * UG;
#pragma unroll
                for (int i = 0; i < UG; ++i) {
                    const float* sl = sb + i * STEP_S;
                    float s = (sl[0] + sl[4]) + (sl[8] + sl[12]);
                    s += (sl[16] + sl[20]) + (sl[24] + sl[28]);
                    int t = tbase + i;
                    out[t * (6 * B_LEN) + b * 6 + 3 + j] = s * 0.125f;
                }
            }
            BAR_ARRIVE(3 + slot);
        }
    }
}

// ---------------------------------------------------------------------------
extern "C" void kernel_launch(void* const* d_in, const int* in_sizes, int n_in,
                              void* d_out, int out_size) {
    const float* x   = (const float*)d_in[0];   // (730,1000,2)
    const float* raw = (const float*)d_in[1];   // (1000,34)
    float* out = (float*)d_out;                 // (730,1000,6)

    fused_kernel<<<NBLK, BLK_T>>>(x, raw, out);
}